// round 15
// baseline (speedup 1.0000x reference)
#include <cuda_runtime.h>
#include <math.h>

#define G     15
#define NB    4
#define NPTS  300000
#define PPC   (NB*NPTS)

// padded grid: [B][12][19 planes][19 rows][24 cols]
#define PLANE 456
#define CSTR  8672
#define BSTR  (12*CSTR)
#define GRIDN (NB*BSTR)

typedef unsigned long long ull;

__device__ float  g_grid[GRIDN];
__device__ float  g_bufA[NB*8*512];
__device__ float  g_bufB[NB*8*512];
__device__ float2 g_slots0[256];   // [oc][b*8+od]
__device__ float2 g_slots1[256];
__device__ unsigned g_flags[256];
__device__ unsigned g_phasev = 0;

// ---------------- helpers ---------------------------------------------------
__device__ __forceinline__ ull pack2(float lo, float hi){
    ull r; asm("mov.b64 %0, {%1,%2};" : "=l"(r) : "f"(lo), "f"(hi)); return r;
}
__device__ __forceinline__ void unpack2(ull v, float& lo, float& hi){
    asm("mov.b64 {%0,%1}, %2;" : "=f"(lo), "=f"(hi) : "l"(v));
}
__device__ __forceinline__ ull fma2(ull a, ull b, ull c){
    ull d; asm("fma.rn.f32x2 %0, %1, %2, %3;" : "=l"(d) : "l"(a), "l"(b), "l"(c)); return d;
}
__device__ __forceinline__ float eluf(float x){ return x > 0.f ? x : (__expf(x)-1.f); }
__device__ __forceinline__ ull elu2(ull v){
    float lo, hi; unpack2(v, lo, hi);
    return pack2(eluf(lo), eluf(hi));
}

// flag-based grid barrier over 256 blocks (block0 parallel detect + release)
__device__ __forceinline__ void gridBar(int t, int bid){
    __shared__ unsigned sMy;
    __syncthreads();
    __threadfence();
    if (t==0) sMy = *((volatile unsigned*)&g_phasev);
    __syncthreads();
    unsigned nxt = sMy + 1u;
    if (bid == 0){
        if (t < 255){
            while (((volatile unsigned*)g_flags)[t+1] != nxt) { }
        }
        __syncthreads();
        __threadfence();
        if (t==0) *((volatile unsigned*)&g_phasev) = nxt;
    } else {
        if (t==0){
            ((volatile unsigned*)g_flags)[bid] = nxt;
            while (*((volatile unsigned*)&g_phasev) != nxt) { }
        }
    }
    __syncthreads();
    __threadfence();
}

// two-value reduction over 256 threads (8 warps)
__device__ __forceinline__ float2 blockRed2(float a, float b, float* sm, int t){
    #pragma unroll
    for (int o=16;o;o>>=1){
        a += __shfl_xor_sync(0xffffffffu, a, o);
        b += __shfl_xor_sync(0xffffffffu, b, o);
    }
    if ((t&31)==0){ sm[(t>>5)*2]=a; sm[(t>>5)*2+1]=b; }
    __syncthreads();
    float2 r;
    r.x = (sm[0]+sm[2])+(sm[4]+sm[6])+(sm[8]+sm[10])+(sm[12]+sm[14]);
    r.y = (sm[1]+sm[3])+(sm[5]+sm[7])+(sm[9]+sm[11])+(sm[13]+sm[15]);
    return r;
}

// BN stats over 256 slots: 8 channels x 32 slots, one warp-read per channel
__device__ __forceinline__ void bnStats(const float2* slots,
                                        const float* gin, const float* bin,
                                        float* sSc, float* sSh, int t)
{
    int ic = t>>5, q = t&31;
    float2 p = *(const float2*)&slots[ic*32+q];
    float sx = p.x, sy = p.y;
    #pragma unroll
    for (int o=16;o;o>>=1){
        sx += __shfl_xor_sync(0xffffffffu, sx, o);
        sy += __shfl_xor_sync(0xffffffffu, sy, o);
    }
    if (q == 0){
        float m  = sx*(1.f/2048.f);
        float vr = sy*(1.f/2048.f) - m*m;
        float sc = gin[ic]*rsqrtf(vr + 1e-5f);
        sSc[ic]=sc; sSh[ic]=bin[ic]-m*sc;
    }
}

// ---------------- point stage: 2 pts/thread, k-outer, channel-pair weights --
__device__ __forceinline__ void disty6(float px, float py, float pz,
                                       float f[6], int& cellpad)
{
    const float CLIPHI = 15.0f - 1e-4f;
    float cx = floorf(fminf(fmaxf(px,0.f), CLIPHI));
    float cy = floorf(fminf(fmaxf(py,0.f), CLIPHI));
    float cz = floorf(fminf(fmaxf(pz,0.f), CLIPHI));
    float ocx = px-cx-0.5f, ocy = py-cy-0.5f, ocz = pz-cz-0.5f;
    float lx = ocx+0.5f, ly = ocy+0.5f, lz = ocz+0.5f;
    float ux = ocx-0.5f, uy = ocy-0.5f, uz = ocz-0.5f;
    f[0]=ocx; f[1]=ocy; f[2]=ocz;
    f[3] = sqrtf(ocx*ocx+ocy*ocy+ocz*ocz);
    f[4] = sqrtf(lx*lx+ly*ly+lz*lz);
    f[5] = sqrtf(ux*ux+uy*uy+uz*uz);
    cellpad = ((int)cx+2)*PLANE + ((int)cy+2)*24 + ((int)cz+2);
}

__global__ void __launch_bounds__(256,2)
point_kernel(const float* __restrict__ P0, const float* __restrict__ P1,
             const float* __restrict__ P2,
             const float* __restrict__ W1, const float* __restrict__ B1,
             const float* __restrict__ W2, const float* __restrict__ B2,
             const float* __restrict__ W3, const float* __restrict__ B3)
{
    __shared__ __align__(16) ull pW1[48], pW2[128], pW3[32];
    __shared__ ull pb1[8], pb2[8], pb3[2];
    int t = threadIdx.x;

    if (t < 48){
        int k = t>>3, jp = t&7, j0 = 2*jp, j1 = 2*jp+1;
        float w0, w1v;
        if (k < 3){
            w0  = W1[k*16+j0]+W1[(k+3)*16+j0]+W1[(k+6)*16+j0];
            w1v = W1[k*16+j1]+W1[(k+3)*16+j1]+W1[(k+6)*16+j1];
        } else {
            w0  = W1[(k+6)*16+j0];
            w1v = W1[(k+6)*16+j1];
        }
        pW1[k*8+jp] = pack2(w0, w1v);
    }
    if (t < 8){
        int j0 = 2*t, j1 = 2*t+1;
        float be0 = B1[j0] + 0.5f*((W1[3*16+j0]+W1[4*16+j0]+W1[5*16+j0])
                                 - (W1[6*16+j0]+W1[7*16+j0]+W1[8*16+j0]));
        float be1 = B1[j1] + 0.5f*((W1[3*16+j1]+W1[4*16+j1]+W1[5*16+j1])
                                 - (W1[6*16+j1]+W1[7*16+j1]+W1[8*16+j1]));
        pb1[t] = pack2(be0, be1);
        pb2[t] = pack2(B2[j0], B2[j1]);
    }
    if (t < 128){
        int k = t>>3, jp = t&7;
        pW2[k*8+jp] = pack2(W2[k*16+2*jp], W2[k*16+2*jp+1]);
    }
    if (t < 32){
        int k = t>>1, jp = t&1;
        pW3[k*2+jp] = pack2(W3[k*4+2*jp], W3[k*4+2*jp+1]);
    }
    if (t < 2) pb3[t] = pack2(B3[2*t], B3[2*t+1]);
    __syncthreads();

    const float* pts = (blockIdx.y==0) ? P0 : (blockIdx.y==1 ? P1 : P2);
    int chan = blockIdx.y*4;

    long p0 = ((long)blockIdx.x*256 + t)*2;
    if (p0 >= PPC) return;

    const float2* v = (const float2*)(pts + p0*3);
    float2 q0=v[0], q1=v[1], q2=v[2];
    int b = (int)(p0 / NPTS);

    float fA[6], fB[6]; int cA, cB;
    disty6(q0.x, q0.y, q1.x, fA, cA);
    disty6(q1.y, q2.x, q2.y, fB, cB);

    // ---- layer 1 (k-outer): 6 eff inputs -> 16 ch (8 pairs) x 2 pts --------
    ull aA[8], aB[8];
    #pragma unroll
    for (int jp=0;jp<8;jp++){ aA[jp]=pb1[jp]; aB[jp]=pb1[jp]; }
    #pragma unroll
    for (int k=0;k<6;k++){
        ull xA = pack2(fA[k], fA[k]);
        ull xB = pack2(fB[k], fB[k]);
        #pragma unroll
        for (int jp=0;jp<8;jp++){
            ull w = pW1[k*8+jp];
            aA[jp] = fma2(xA, w, aA[jp]);
            aB[jp] = fma2(xB, w, aB[jp]);
        }
    }
    ull hA[8], hB[8];
    #pragma unroll
    for (int jp=0;jp<8;jp++){ hA[jp]=elu2(aA[jp]); hB[jp]=elu2(aB[jp]); }

    // ---- layer 2 (kp-outer, single unpack per pair): 16 -> 16 x 2 pts ------
    #pragma unroll
    for (int jp=0;jp<8;jp++){ aA[jp]=pb2[jp]; aB[jp]=pb2[jp]; }
    #pragma unroll
    for (int kp=0;kp<8;kp++){
        float sA0, sA1, sB0, sB1;
        unpack2(hA[kp], sA0, sA1);
        unpack2(hB[kp], sB0, sB1);
        ull xA0 = pack2(sA0,sA0), xA1 = pack2(sA1,sA1);
        ull xB0 = pack2(sB0,sB0), xB1 = pack2(sB1,sB1);
        #pragma unroll
        for (int jp=0;jp<8;jp++){
            ull w0 = pW2[(2*kp)*8+jp];
            ull w1 = pW2[(2*kp+1)*8+jp];
            aA[jp] = fma2(xA0, w0, aA[jp]);
            aB[jp] = fma2(xB0, w0, aB[jp]);
            aA[jp] = fma2(xA1, w1, aA[jp]);
            aB[jp] = fma2(xB1, w1, aB[jp]);
        }
    }
    #pragma unroll
    for (int jp=0;jp<8;jp++){ hA[jp]=elu2(aA[jp]); hB[jp]=elu2(aB[jp]); }

    // ---- layer 3 (kp-outer): 16 -> 4 (2 pairs) x 2 pts + scatter-max -------
    ull oA[2], oB[2];
    oA[0]=pb3[0]; oA[1]=pb3[1]; oB[0]=pb3[0]; oB[1]=pb3[1];
    #pragma unroll
    for (int kp=0;kp<8;kp++){
        float sA0, sA1, sB0, sB1;
        unpack2(hA[kp], sA0, sA1);
        unpack2(hB[kp], sB0, sB1);
        ull xA0 = pack2(sA0,sA0), xA1 = pack2(sA1,sA1);
        ull xB0 = pack2(sB0,sB0), xB1 = pack2(sB1,sB1);
        #pragma unroll
        for (int jp=0;jp<2;jp++){
            ull w0 = pW3[(2*kp)*2+jp];
            ull w1 = pW3[(2*kp+1)*2+jp];
            oA[jp] = fma2(xA0, w0, oA[jp]);
            oB[jp] = fma2(xB0, w0, oB[jp]);
            oA[jp] = fma2(xA1, w1, oA[jp]);
            oB[jp] = fma2(xB1, w1, oB[jp]);
        }
    }
    int baseA = b*BSTR + chan*CSTR + cA;
    int baseB = b*BSTR + chan*CSTR + cB;
    #pragma unroll
    for (int jp=0;jp<2;jp++){
        float v0, v1; unpack2(oA[jp], v0, v1);
        if (v0 > 0.f) atomicMax((int*)&g_grid[baseA + (2*jp  )*CSTR], __float_as_int(v0));
        if (v1 > 0.f) atomicMax((int*)&g_grid[baseA + (2*jp+1)*CSTR], __float_as_int(v1));
        float u0, u1; unpack2(oB[jp], u0, u1);
        if (u0 > 0.f) atomicMax((int*)&g_grid[baseB + (2*jp  )*CSTR], __float_as_int(u0));
        if (u1 > 0.f) atomicMax((int*)&g_grid[baseB + (2*jp+1)*CSTR], __float_as_int(u1));
    }
}

// ---------------- fused conv stack: 256 blocks x 256 threads, 2 blocks/SM ---
// grid 256 = (oc8, b4, od8); convs thread = (cic8, oh8, owh2, kdh2).
__global__ void __launch_bounds__(256,2)
conv_stack_kernel(const float* __restrict__ w1,
                  const float* __restrict__ wS,
                  const float* __restrict__ bn1_g, const float* __restrict__ bn1_b,
                  const float* __restrict__ bns_g, const float* __restrict__ bns_b,
                  float* __restrict__ outp)
{
    __shared__ __align__(16) float sIn[6912];    // [8 ic][6 dd][12 h][12 w]
    __shared__ __align__(16) float wsm[1600];    // [8 ic][5 kd][5 kh][8 pad]
    __shared__ __align__(16) float sAcc[1024];   // [16 part][64 out]
    __shared__ float sSc[8], sSh[8], sred[16];

    int bid = blockIdx.x;
    int oc = bid & 7, b = (bid>>3) & 3, od = bid>>5;   // od 0..7
    int t = threadIdx.x;
    int kdh  = t&1;           // kd split: 0 -> kd 0..2, 1 -> kd 3..4
    int owh  = (t>>1)&1;      // ow half
    int coh  = (t>>2)&7;
    int cic  = t>>5;          // 0..7
    int obase = b*4096 + oc*512 + od*64;

    { // zero sIn halo once
        float4 z4 = make_float4(0.f,0.f,0.f,0.f);
        for (int i=t;i<1728;i+=256) ((float4*)sIn)[i] = z4;
    }

    // ================= conv1: 12->8, k5, s2, p2, direct-from-L2 =============
    // t<192: (cic1 12, oh1 8, owh1 2) -> 4 ow each, full kd range
    float accL = 0.f;
    {
        if (t < 192){
            int owh1 = t&1, oh1 = (t>>1)&7, cic1 = t>>4;
            float a[4] = {0.f,0.f,0.f,0.f};
            const float* gch = g_grid + (b*12+cic1)*CSTR;
            const float* wp0 = w1 + (oc*12+cic1)*125;
            #pragma unroll
            for (int kd=0;kd<5;kd++){
                #pragma unroll
                for (int kh=0;kh<5;kh++){
                    const float* row = gch + (2*od+kd)*PLANE + (2*oh1+kh)*24 + 8*owh1;
                    float4 r0 = *(const float4*)(row);
                    float4 r1 = *(const float4*)(row+4);
                    float4 r2 = *(const float4*)(row+8);
                    float rr[12] = {r0.x,r0.y,r0.z,r0.w, r1.x,r1.y,r1.z,r1.w,
                                    r2.x,r2.y,r2.z,r2.w};
                    const float* wp = wp0 + kd*25 + kh*5;
                    float wk0=__ldg(wp), wk1=__ldg(wp+1), wk2=__ldg(wp+2),
                          wk3=__ldg(wp+3), wk4=__ldg(wp+4);
                    #pragma unroll
                    for (int o=0;o<4;o++){
                        a[o] += rr[2*o+0]*wk0;
                        a[o] += rr[2*o+1]*wk1;
                        a[o] += rr[2*o+2]*wk2;
                        a[o] += rr[2*o+3]*wk3;
                        a[o] += rr[2*o+4]*wk4;
                    }
                }
            }
            int oidx = oh1*8 + owh1*4;
            #pragma unroll
            for (int o=0;o<4;o++) sAcc[cic1*64 + oidx + o] = a[o];
        }
        __syncthreads();

        float s = 0.f;
        if (t < 64){
            #pragma unroll
            for (int ic=0;ic<12;ic++) s += sAcc[ic*64 + t];
            __stcg(&g_bufA[obase + t], s);
        }
        accL = s;
        float2 r = blockRed2(t<64 ? s : 0.f, t<64 ? s*s : 0.f, sred, t);
        if (t==0){ g_slots0[oc*32 + b*8 + od] = r; }
    }
    gridBar(t, bid);

    // ================= 6x (input BN+ELU -> conv 8->8 k5 p2) =================
    for (int L=0; L<6; L++){
        int dir = L & 1;
        const float*  rin  = dir ? g_bufB   : g_bufA;
        float*        rout = dir ? g_bufA   : g_bufB;
        const float2* sinp = dir ? g_slots1 : g_slots0;
        float2*       sout = dir ? g_slots0 : g_slots1;
        const float*  gin  = (L==0) ? bn1_g : (bns_g + (L-1)*8);
        const float*  bin  = (L==0) ? bn1_b : (bns_b + (L-1)*8);
        const float*  w    = wS + L*8000;

        // issue fill loads first (depend only on gridBar), overlap with stats
        float4 vv[3]; bool ok[3]; int di[3]; int icu[3];
        #pragma unroll
        for (int u=0;u<3;u++){
            int i = t + u*256;
            int half = i&1, h = (i>>1)&7, dd = (i>>4)%6, ic = i/96;
            int id = od - 2 + dd;
            ok[u]  = (unsigned)id < 8u;
            icu[u] = ic;
            di[u]  = ic*864 + dd*144 + (h+2)*12 + 2 + half*4;
            if (ok[u])
                vv[u] = __ldcg((const float4*)(rin + b*4096 + ic*512 + id*64 + h*8 + half*4));
        }
        for (int i=t;i<1000;i+=256){
            int ic=i/125, r=i%125, kd=r/25, kh=(r%25)/5, kw=r%5;
            wsm[((ic*5+kd)*5+kh)*8 + kw] = w[oc*1000 + i];
        }
        bnStats(sinp, gin, bin, sSc, sSh, t);
        __syncthreads();

        #pragma unroll
        for (int u=0;u<3;u++){
            if (ok[u]){
                float sc = sSc[icu[u]], sh = sSh[icu[u]];
                float* d = sIn + di[u];
                d[0]=eluf(vv[u].x*sc+sh); d[1]=eluf(vv[u].y*sc+sh);
                d[2]=eluf(vv[u].z*sc+sh); d[3]=eluf(vv[u].w*sc+sh);
            }
        }
        __syncthreads();

        // conv: thread computes 4 ow over its kd range
        {
            float a[4] = {0.f,0.f,0.f,0.f};
            const float* cb = sIn + cic*864;
            const float* wb = wsm + cic*200;
            int kd0 = kdh ? 3 : 0;
            int kd1 = kdh ? 5 : 3;
            for (int kd=kd0; kd<kd1; kd++){
                #pragma unroll
                for (int kh=0;kh<5;kh++){
                    const float* row = cb + kd*144 + (coh+kh)*12 + owh*4;
                    float4 r0 = *(const float4*)(row);
                    float4 r1 = *(const float4*)(row+4);
                    float rr[8] = {r0.x,r0.y,r0.z,r0.w, r1.x,r1.y,r1.z,r1.w};
                    const float* wp = wb + (kd*5+kh)*8;
                    float4 wv = *(const float4*)wp;
                    float wk4 = wp[4];
                    #pragma unroll
                    for (int o=0;o<4;o++){
                        a[o] += rr[o+0]*wv.x;
                        a[o] += rr[o+1]*wv.y;
                        a[o] += rr[o+2]*wv.z;
                        a[o] += rr[o+3]*wv.w;
                        a[o] += rr[o+4]*wk4;
                    }
                }
            }
            int oidx = coh*8 + owh*4;
            #pragma unroll
            for (int o=0;o<4;o++) sAcc[(cic*2+kdh)*64 + oidx + o] = a[o];
        }
        __syncthreads();

        float s = 0.f;
        if (t < 64){
            #pragma unroll
            for (int j=0;j<16;j++) s += sAcc[j*64 + t];
            __stcg(&rout[obase + t], s);
        }
        accL = s;
        float2 r = blockRed2(t<64 ? s : 0.f, t<64 ? s*s : 0.f, sred, t);
        if (t==0){ sout[oc*32 + b*8 + od] = r; }
        gridBar(t, bid);
    }

    // ================= final BN+ELU from live accumulator ===================
    // L=5 (dir=1) wrote stats to slots0
    {
        if (t < 32){
            float2 p = *(const float2*)&g_slots0[oc*32 + t];
            float sx = p.x, sy = p.y;
            #pragma unroll
            for (int o=16;o;o>>=1){
                sx += __shfl_xor_sync(0xffffffffu, sx, o);
                sy += __shfl_xor_sync(0xffffffffu, sy, o);
            }
            if (t==0){
                float m  = sx*(1.f/2048.f);
                float vr = sy*(1.f/2048.f) - m*m;
                float sc = bns_g[40+oc]*rsqrtf(vr + 1e-5f);
                sSc[0]=sc; sSh[0]=bns_b[40+oc]-m*sc;
            }
        }
        __syncthreads();
        if (t < 64){
            float sc = sSc[0], sh = sSh[0];
            outp[(b*8+oc)*512 + od*64 + t] = eluf(accL*sc+sh);
        }
    }
}

// ---------------------------------------------------------------------------
extern "C" void kernel_launch(void* const* d_in, const int* in_sizes, int n_in,
                              void* d_out, int out_size)
{
    const float* goals       = (const float*)d_in[0];
    const float* inputs      = (const float*)d_in[1];
    const float* backgrounds = (const float*)d_in[2];
    const float* W1 = (const float*)d_in[3];
    const float* b1 = (const float*)d_in[4];
    const float* W2 = (const float*)d_in[5];
    const float* b2 = (const float*)d_in[6];
    const float* W3 = (const float*)d_in[7];
    const float* b3 = (const float*)d_in[8];
    const float* conv1_w = (const float*)d_in[9];
    const float* bn1_g   = (const float*)d_in[11];
    const float* bn1_b   = (const float*)d_in[12];
    const float* convs_w = (const float*)d_in[13];
    const float* bns_g   = (const float*)d_in[15];
    const float* bns_b   = (const float*)d_in[16];
    float* out = (float*)d_out;

    void* gptr = nullptr;
    cudaGetSymbolAddress(&gptr, g_grid);
    cudaMemsetAsync(gptr, 0, GRIDN*sizeof(float));

    dim3 pg((PPC/2 + 255)/256, 3);
    point_kernel<<<pg,256>>>(inputs, goals, backgrounds, W1,b1,W2,b2,W3,b3);

    conv_stack_kernel<<<256,256>>>(conv1_w, convs_w, bn1_g, bn1_b,
                                   bns_g, bns_b, out);
}